// round 1
// baseline (speedup 1.0000x reference)
#include <cuda_runtime.h>
#include <cstdint>
#include <cstddef>

#define NN   50000
#define EE   800000
#define RR   4
#define DIN  128
#define DH   256
#define EPSF 1e-10f

// ---------------- scratch (static device globals; no cudaMalloc allowed) ----
__device__ float g_cnt[NN * RR];                       // edge count per (node, rel)
__device__ float g_agg[(size_t)NN * RR * DH];          // max layer-2 size: 204.8 MB
__device__ float g_t[(size_t)NN * DH];                 // RGC output
__device__ float g_pg[(size_t)NN * 2 * DH];            // highway proj|gate pre-activations
__device__ float g_h[(size_t)NN * DH];                 // highway output (layer-1 -> layer-2 input)

// ---------------- elementwise helpers ---------------------------------------
__global__ void zero_kernel(float4* __restrict__ p, int n4) {
    int i = blockIdx.x * blockDim.x + threadIdx.x;
    if (i < n4) p[i] = make_float4(0.f, 0.f, 0.f, 0.f);
}

__global__ void count_kernel(const int* __restrict__ dst, const int* __restrict__ rel, int E) {
    int e = blockIdx.x * blockDim.x + threadIdx.x;
    if (e < E) atomicAdd(&g_cnt[dst[e] * RR + rel[e]], 1.0f);
}

// one warp per edge; lanes cover the feature row in float4 chunks
template <int D>
__global__ void scatter_kernel(const float* __restrict__ x,
                               const int* __restrict__ src,
                               const int* __restrict__ dst,
                               const int* __restrict__ rel, int E) {
    int gt   = blockIdx.x * blockDim.x + threadIdx.x;
    int e    = gt >> 5;
    int lane = threadIdx.x & 31;
    if (e >= E) return;
    int s = src[e];
    int b = dst[e] * RR + rel[e];
    const float4* xin = (const float4*)(x + (size_t)s * D);
    float* out = g_agg + (size_t)b * D;
#pragma unroll
    for (int j4 = lane; j4 < D / 4; j4 += 32) {
        float4 v = xin[j4];
        atomicAdd(out + j4 * 4 + 0, v.x);
        atomicAdd(out + j4 * 4 + 1, v.y);
        atomicAdd(out + j4 * 4 + 2, v.z);
        atomicAdd(out + j4 * 4 + 3, v.w);
    }
}

// agg[b, :] *= 1/(cnt[b] + eps), vectorized
template <int D>
__global__ void scale_kernel(int nbuckets) {
    int i = blockIdx.x * blockDim.x + threadIdx.x;   // over nbuckets * D/4
    if (i >= nbuckets * (D / 4)) return;
    int b = i / (D / 4);
    float inv = 1.0f / (g_cnt[b] + EPSF);
    float4* p = (float4*)g_agg;
    float4 v = p[i];
    v.x *= inv; v.y *= inv; v.z *= inv; v.w *= inv;
    p[i] = v;
}

// h = sigmoid(gate) * relu(proj) + (1 - sigmoid(gate)) * t
__global__ void highway_kernel(const float* __restrict__ t, const float* __restrict__ pg,
                               float* __restrict__ h, int M) {
    int i = blockIdx.x * blockDim.x + threadIdx.x;   // over M*DH
    if (i >= M * DH) return;
    int n = i >> 8;        // /256
    int c = i & 255;
    float p = pg[(size_t)n * (2 * DH) + c];
    float g = pg[(size_t)n * (2 * DH) + DH + c];
    p = fmaxf(p, 0.0f);
    g = 1.0f / (1.0f + expf(-g));
    h[i] = g * p + (1.0f - g) * t[i];
}

// ---------------- fused dual-A GEMM ------------------------------------------
// C[M, Nout] = act( A1[M,K1] @ W1[K1,Nout] + A2[M,K2] @ W2[K2,Nout] + b1 + b2 )
// row-major everywhere; ldc selectable so we can write into halves of g_pg.
#define BM 128
#define BN 128
#define BK 16

__global__ __launch_bounds__(256)
void gemm2_kernel(const float* __restrict__ A1, int K1, const float* __restrict__ W1,
                  const float* __restrict__ A2, int K2, const float* __restrict__ W2,
                  const float* __restrict__ b1, const float* __restrict__ b2,
                  float* __restrict__ C, int M, int Nout, int ldc, int act) {
    __shared__ float As[BK][BM];
    __shared__ float Bs[BK][BN];
    int tid = threadIdx.x;
    int tx = tid & 15;           // 16 col-groups of 8
    int ty = tid >> 4;           // 16 row-groups of 8
    int rowBase = blockIdx.x * BM;
    int colBase = blockIdx.y * BN;

    float acc[8][8];
#pragma unroll
    for (int i = 0; i < 8; i++)
#pragma unroll
        for (int j = 0; j < 8; j++) acc[i][j] = 0.f;

    int nt1 = K1 >> 4, nt2 = K2 >> 4;
    for (int t = 0; t < nt1 + nt2; ++t) {
        const float *A, *W;
        int K, k0;
        if (t < nt1) { A = A1; W = W1; K = K1; k0 = t * BK; }
        else         { A = A2; W = W2; K = K2; k0 = (t - nt1) * BK; }

        // A tile: 128 rows x 16 cols = 512 float4, 2 per thread; store transposed
#pragma unroll
        for (int i = 0; i < 2; ++i) {
            int li = tid + i * 256;
            int r  = li >> 2;
            int c4 = (li & 3) << 2;
            float4 v = make_float4(0.f, 0.f, 0.f, 0.f);
            int gr = rowBase + r;
            if (gr < M) v = *(const float4*)(A + (size_t)gr * K + k0 + c4);
            As[c4 + 0][r] = v.x;
            As[c4 + 1][r] = v.y;
            As[c4 + 2][r] = v.z;
            As[c4 + 3][r] = v.w;
        }
        // B tile: 16 rows x 128 cols = 512 float4, 2 per thread
#pragma unroll
        for (int i = 0; i < 2; ++i) {
            int li = tid + i * 256;
            int r  = li >> 5;
            int c4 = (li & 31) << 2;
            float4 v = *(const float4*)(W + (size_t)(k0 + r) * Nout + colBase + c4);
            *(float4*)&Bs[r][c4] = v;
        }
        __syncthreads();

#pragma unroll
        for (int kk = 0; kk < BK; ++kk) {
            float a[8], b[8];
#pragma unroll
            for (int i = 0; i < 8; i++) a[i] = As[kk][ty * 8 + i];
#pragma unroll
            for (int j = 0; j < 8; j++) b[j] = Bs[kk][tx * 8 + j];
#pragma unroll
            for (int i = 0; i < 8; i++)
#pragma unroll
                for (int j = 0; j < 8; j++)
                    acc[i][j] = fmaf(a[i], b[j], acc[i][j]);
        }
        __syncthreads();
    }

#pragma unroll
    for (int i = 0; i < 8; i++) {
        int gr = rowBase + ty * 8 + i;
        if (gr >= M) continue;
#pragma unroll
        for (int j = 0; j < 8; j++) {
            int gc = colBase + tx * 8 + j;
            float v = acc[i][j];
            if (b1) v += b1[gc];
            if (b2) v += b2[gc];
            if (act) v = fmaxf(v, 0.0f);
            C[(size_t)gr * ldc + gc] = v;
        }
    }
}

// ---------------- launcher ----------------------------------------------------
extern "C" void kernel_launch(void* const* d_in, const int* in_sizes, int n_in,
                              void* d_out, int out_size) {
    const float* x       = (const float*)d_in[0];
    const int*   src     = (const int*)d_in[1];
    const int*   dst     = (const int*)d_in[2];
    const int*   rel     = (const int*)d_in[3];
    const float* rel_w1  = (const float*)d_in[4];
    const float* rel_b1  = (const float*)d_in[5];
    const float* loop_w1 = (const float*)d_in[6];
    const float* loop_b1 = (const float*)d_in[7];
    const float* hp_w1   = (const float*)d_in[8];
    const float* hp_b1   = (const float*)d_in[9];
    const float* ht_w1   = (const float*)d_in[10];
    const float* ht_b1   = (const float*)d_in[11];
    const float* rel_w2  = (const float*)d_in[12];
    const float* rel_b2  = (const float*)d_in[13];
    const float* loop_w2 = (const float*)d_in[14];
    const float* loop_b2 = (const float*)d_in[15];
    const float* hp_w2   = (const float*)d_in[16];
    const float* hp_b2   = (const float*)d_in[17];
    const float* ht_w2   = (const float*)d_in[18];
    const float* ht_b2   = (const float*)d_in[19];
    float* out = (float*)d_out;

    float *agg, *cnt, *tbuf, *pg, *hbuf;
    cudaGetSymbolAddress((void**)&agg,  g_agg);
    cudaGetSymbolAddress((void**)&cnt,  g_cnt);
    cudaGetSymbolAddress((void**)&tbuf, g_t);
    cudaGetSymbolAddress((void**)&pg,   g_pg);
    cudaGetSymbolAddress((void**)&hbuf, g_h);

    const int M = NN, E = EE;
    const int TPB = 256;
    dim3 gemm_grid((M + BM - 1) / BM, DH / BN);   // (391, 2)

    // ---- counts (identical for both layers) ----
    zero_kernel<<<(NN * RR / 4 + TPB - 1) / TPB, TPB>>>((float4*)cnt, NN * RR / 4);
    count_kernel<<<(E + TPB - 1) / TPB, TPB>>>(dst, rel, E);

    // ---- layer 1: RGC(128 -> 256) ----
    {
        int n4 = NN * RR * DIN / 4;
        zero_kernel<<<(n4 + TPB - 1) / TPB, TPB>>>((float4*)agg, n4);
    }
    scatter_kernel<DIN><<<(E * 32 + TPB - 1) / TPB, TPB>>>(x, src, dst, rel, E);
    scale_kernel<DIN><<<(NN * RR * (DIN / 4) + TPB - 1) / TPB, TPB>>>(NN * RR);
    gemm2_kernel<<<gemm_grid, TPB>>>(agg, RR * DIN, rel_w1, x, DIN, loop_w1,
                                     rel_b1, loop_b1, tbuf, M, DH, DH, 1);
    // highway 1
    gemm2_kernel<<<gemm_grid, TPB>>>(tbuf, DH, hp_w1, nullptr, 0, nullptr,
                                     hp_b1, nullptr, pg, M, DH, 2 * DH, 0);
    gemm2_kernel<<<gemm_grid, TPB>>>(tbuf, DH, ht_w1, nullptr, 0, nullptr,
                                     ht_b1, nullptr, pg + DH, M, DH, 2 * DH, 0);
    highway_kernel<<<(M * DH + TPB - 1) / TPB, TPB>>>(tbuf, pg, hbuf, M);

    // ---- layer 2: RGC(256 -> 256) ----
    {
        int n4 = NN * RR * DH / 4;
        zero_kernel<<<(n4 + TPB - 1) / TPB, TPB>>>((float4*)agg, n4);
    }
    scatter_kernel<DH><<<(E * 32 + TPB - 1) / TPB, TPB>>>(hbuf, src, dst, rel, E);
    scale_kernel<DH><<<(NN * RR * (DH / 4) + TPB - 1) / TPB, TPB>>>(NN * RR);
    gemm2_kernel<<<gemm_grid, TPB>>>(agg, RR * DH, rel_w2, hbuf, DH, loop_w2,
                                     rel_b2, loop_b2, tbuf, M, DH, DH, 1);
    // highway 2 (final output straight into d_out)
    gemm2_kernel<<<gemm_grid, TPB>>>(tbuf, DH, hp_w2, nullptr, 0, nullptr,
                                     hp_b2, nullptr, pg, M, DH, 2 * DH, 0);
    gemm2_kernel<<<gemm_grid, TPB>>>(tbuf, DH, ht_w2, nullptr, 0, nullptr,
                                     ht_b2, nullptr, pg + DH, M, DH, 2 * DH, 0);
    highway_kernel<<<(M * DH + TPB - 1) / TPB, TPB>>>(tbuf, pg, out, M);
}

// round 3
// speedup vs baseline: 1.7960x; 1.7960x over previous
#include <cuda_runtime.h>
#include <cuda_bf16.h>
#include <cstdint>
#include <cstddef>

#define NN   50000
#define EE   800000
#define RR   4
#define DIN  128
#define DH   256
#define EPSF 1e-10f

// ---------------- scratch (static device globals; no cudaMalloc allowed) ----
__device__ float g_cnt[NN * RR];
__device__ float g_agg[(size_t)NN * RR * DH];
__device__ float g_t[(size_t)NN * DH];
__device__ float g_pg[(size_t)NN * 2 * DH];
__device__ float g_h[(size_t)NN * DH];

// ---------------- elementwise helpers -----------------------------------------
__global__ void zero_kernel(float4* __restrict__ p, int n4) {
    int i = blockIdx.x * blockDim.x + threadIdx.x;
    if (i < n4) p[i] = make_float4(0.f, 0.f, 0.f, 0.f);
}

__global__ void count_kernel(const int* __restrict__ dst, const int* __restrict__ rel, int E) {
    int e = blockIdx.x * blockDim.x + threadIdx.x;
    if (e < E) atomicAdd(&g_cnt[dst[e] * RR + rel[e]], 1.0f);
}

template <int D>
__global__ void scatter_kernel(const float* __restrict__ x,
                               const int* __restrict__ src,
                               const int* __restrict__ dst,
                               const int* __restrict__ rel, int E) {
    int gt = blockIdx.x * blockDim.x + threadIdx.x;
    int e = gt >> 5;
    int lane = threadIdx.x & 31;
    if (e >= E) return;
    int s = src[e];
    int b = dst[e] * RR + rel[e];
    const float4* xin = (const float4*)(x + (size_t)s * D);
    float* out = g_agg + (size_t)b * D;
#pragma unroll
    for (int j4 = lane; j4 < D / 4; j4 += 32) {
        float4 v = xin[j4];
        atomicAdd(out + j4 * 4 + 0, v.x);
        atomicAdd(out + j4 * 4 + 1, v.y);
        atomicAdd(out + j4 * 4 + 2, v.z);
        atomicAdd(out + j4 * 4 + 3, v.w);
    }
}

template <int D>
__global__ void scale_kernel(int nbuckets) {
    int i = blockIdx.x * blockDim.x + threadIdx.x;
    if (i >= nbuckets * (D / 4)) return;
    int b = i / (D / 4);
    float inv = 1.0f / (g_cnt[b] + EPSF);
    float4* p = (float4*)g_agg;
    float4 v = p[i];
    v.x *= inv; v.y *= inv; v.z *= inv; v.w *= inv;
    p[i] = v;
}

__global__ void highway_kernel(const float* __restrict__ t, const float* __restrict__ pg,
                               float* __restrict__ h, int M) {
    int i = blockIdx.x * blockDim.x + threadIdx.x;
    if (i >= M * DH) return;
    int n = i >> 8;
    int c = i & 255;
    float p = pg[(size_t)n * (2 * DH) + c];
    float g = pg[(size_t)n * (2 * DH) + DH + c];
    p = fmaxf(p, 0.0f);
    g = 1.0f / (1.0f + expf(-g));
    h[i] = g * p + (1.0f - g) * t[i];
}

// ---------------- mma.sync bf16 helpers ----------------------------------------
__device__ __forceinline__ uint32_t smem_u32(const void* p) {
    uint32_t a;
    asm("{ .reg .u64 t; cvta.to.shared.u64 t, %1; cvt.u32.u64 %0, t; }" : "=r"(a) : "l"(p));
    return a;
}

__device__ __forceinline__ void ldsm_x4(uint32_t* r, uint32_t addr) {
    asm volatile("ldmatrix.sync.aligned.m8n8.x4.shared.b16 {%0,%1,%2,%3}, [%4];"
                 : "=r"(r[0]), "=r"(r[1]), "=r"(r[2]), "=r"(r[3]) : "r"(addr));
}
__device__ __forceinline__ void ldsm_x4_t(uint32_t* r, uint32_t addr) {
    asm volatile("ldmatrix.sync.aligned.m8n8.x4.trans.shared.b16 {%0,%1,%2,%3}, [%4];"
                 : "=r"(r[0]), "=r"(r[1]), "=r"(r[2]), "=r"(r[3]) : "r"(addr));
}
__device__ __forceinline__ void mma_bf16(float* d, const uint32_t* a, uint32_t b0, uint32_t b1) {
    asm volatile(
        "mma.sync.aligned.m16n8k16.row.col.f32.bf16.bf16.f32 "
        "{%0,%1,%2,%3}, {%4,%5,%6,%7}, {%8,%9}, {%0,%1,%2,%3};"
        : "+f"(d[0]), "+f"(d[1]), "+f"(d[2]), "+f"(d[3])
        : "r"(a[0]), "r"(a[1]), "r"(a[2]), "r"(a[3]), "r"(b0), "r"(b1));
}

// split fp32 -> bf16 hi + bf16 lo (residual)
__device__ __forceinline__ void split_bf(float v, uint16_t& h, uint16_t& l) {
    __nv_bfloat16 hb = __float2bfloat16_rn(v);
    float res = v - __bfloat162float(hb);
    __nv_bfloat16 lb = __float2bfloat16_rn(res);
    h = __bfloat16_as_ushort(hb);
    l = __bfloat16_as_ushort(lb);
}
__device__ __forceinline__ void split4(float4 v, uint2& hi, uint2& lo) {
    uint16_t h0, h1, h2, h3, l0, l1, l2, l3;
    split_bf(v.x, h0, l0); split_bf(v.y, h1, l1);
    split_bf(v.z, h2, l2); split_bf(v.w, h3, l3);
    hi.x = (uint32_t)h0 | ((uint32_t)h1 << 16);
    hi.y = (uint32_t)h2 | ((uint32_t)h3 << 16);
    lo.x = (uint32_t)l0 | ((uint32_t)l1 << 16);
    lo.y = (uint32_t)l2 | ((uint32_t)l3 << 16);
}

// ---------------- bf16-split dual-A GEMM (tensor cores via mma.sync) -----------
// C[M, 256-slice] = act( A1[M,K1] @ W1[K1,256] + A2[M,K2] @ W2[K2,256] + b1 (+b2) )
// block tile 128x128, BK = 16 fp32 per iter (-> 3 bf16 k-steps of 16 via split)
#define A_STRIDE 80                   // bytes per A smem row (40 bf16: hi 16 | lo 16 | pad)
#define A_BYTES  (128 * A_STRIDE)     // 10240
#define B_BYTES  (32 * 256)           // 8192 (rows 0-15 hi, 16-31 lo; XOR-swizzled)
#define STAGE_BYTES (A_BYTES + B_BYTES)

__global__ void __launch_bounds__(256)
gemm_mma(const float* __restrict__ A1, int K1, const float* __restrict__ W1,
         const float* __restrict__ A2, int K2, const float* __restrict__ W2,
         const float* __restrict__ b1, const float* __restrict__ b2,
         float* __restrict__ C, int M, int ldc, int act) {
    __shared__ char sm[2 * STAGE_BYTES];

    int tid  = threadIdx.x;
    int warp = tid >> 5;
    int lane = tid & 31;
    int warpM = warp >> 1;            // 0..3 -> m offset 32*warpM
    int warpN = warp & 1;             // 0..1 -> n offset 64*warpN
    int rowBase = blockIdx.x * 128;
    int colBase = blockIdx.y * 128;

    float acc[2][8][4];
#pragma unroll
    for (int i = 0; i < 2; i++)
#pragma unroll
        for (int j = 0; j < 8; j++)
#pragma unroll
            for (int q = 0; q < 4; q++) acc[i][j][q] = 0.f;

    int nt1 = K1 >> 4, nt2 = K2 >> 4;
    int nt = nt1 + nt2;

    float4 av[2], bv[2];

    // prefetch t = 0
    {
        const float* A = A1; const float* W = W1; int K = K1, k0 = 0;
        if (nt1 == 0) { A = A2; W = W2; K = K2; }
#pragma unroll
        for (int i = 0; i < 2; ++i) {
            int li = tid + i * 256;
            int r = li >> 2, c4 = li & 3;
            int gr = rowBase + r;
            av[i] = (gr < M) ? *(const float4*)(A + (size_t)gr * K + k0 + c4 * 4)
                             : make_float4(0.f, 0.f, 0.f, 0.f);
        }
#pragma unroll
        for (int i = 0; i < 2; ++i) {
            int li = tid + i * 256;
            int r = li >> 5, c4 = li & 31;
            bv[i] = *(const float4*)(W + (size_t)(k0 + r) * DH + colBase + c4 * 4);
        }
    }

    for (int t = 0; t < nt; ++t) {
        char* As = sm + (t & 1) * STAGE_BYTES;
        char* Bs = As + A_BYTES;

        // ---- STS: split fp32 -> bf16 hi/lo tiles ----
#pragma unroll
        for (int i = 0; i < 2; ++i) {
            int li = tid + i * 256;
            int r = li >> 2, c4 = li & 3;
            uint2 hi, lo;
            split4(av[i], hi, lo);
            *(uint2*)(As + r * A_STRIDE + c4 * 8)      = hi;
            *(uint2*)(As + r * A_STRIDE + 32 + c4 * 8) = lo;
        }
#pragma unroll
        for (int i = 0; i < 2; ++i) {
            int li = tid + i * 256;
            int r = li >> 5, c4 = li & 31;
            uint2 hi, lo;
            split4(bv[i], hi, lo);
            uint32_t sw = (uint32_t)(c4 * 8) ^ ((r & 7) << 4);
            *(uint2*)(Bs + r * 256 + sw)        = hi;
            *(uint2*)(Bs + (16 + r) * 256 + sw) = lo;
        }
        __syncthreads();

        // ---- prefetch t+1 (hidden under the mma work below) ----
        if (t + 1 < nt) {
            int tn = t + 1;
            const float* A; const float* W; int K, k0;
            if (tn < nt1) { A = A1; W = W1; K = K1; k0 = tn * 16; }
            else          { A = A2; W = W2; K = K2; k0 = (tn - nt1) * 16; }
#pragma unroll
            for (int i = 0; i < 2; ++i) {
                int li = tid + i * 256;
                int r = li >> 2, c4 = li & 3;
                int gr = rowBase + r;
                av[i] = (gr < M) ? *(const float4*)(A + (size_t)gr * K + k0 + c4 * 4)
                                 : make_float4(0.f, 0.f, 0.f, 0.f);
            }
#pragma unroll
            for (int i = 0; i < 2; ++i) {
                int li = tid + i * 256;
                int r = li >> 5, c4 = li & 31;
                bv[i] = *(const float4*)(W + (size_t)(k0 + r) * DH + colBase + c4 * 4);
            }
        }

        // ---- load fragments (hi & lo) ----
        uint32_t aBase = smem_u32(As);
        uint32_t bBase = smem_u32(Bs);
        uint32_t ahi[2][4], alo[2][4], bhi[4][4], blo[4][4];
#pragma unroll
        for (int mt = 0; mt < 2; ++mt) {
            int row = warpM * 32 + mt * 16 + (lane & 15);
            uint32_t ad = aBase + row * A_STRIDE + ((lane >> 4) * 8) * 2;
            ldsm_x4(ahi[mt], ad);
            ldsm_x4(alo[mt], ad + 32);
        }
#pragma unroll
        for (int bt = 0; bt < 4; ++bt) {
            int k = lane & 15;
            uint32_t cb = (uint32_t)(warpN * 128 + bt * 32 + (lane >> 4) * 16);
            uint32_t bd = bBase + k * 256 + (cb ^ ((k & 7) << 4));
            ldsm_x4_t(bhi[bt], bd);
            ldsm_x4_t(blo[bt], bd + 16 * 256);
        }

        // ---- 3-term split mma: hi*hi + hi*lo + lo*hi ----
#pragma unroll
        for (int mt = 0; mt < 2; ++mt) {
#pragma unroll
            for (int bt = 0; bt < 4; ++bt) {
                mma_bf16(acc[mt][bt * 2 + 0], ahi[mt], bhi[bt][0], bhi[bt][1]);
                mma_bf16(acc[mt][bt * 2 + 1], ahi[mt], bhi[bt][2], bhi[bt][3]);
                mma_bf16(acc[mt][bt * 2 + 0], ahi[mt], blo[bt][0], blo[bt][1]);
                mma_bf16(acc[mt][bt * 2 + 1], ahi[mt], blo[bt][2], blo[bt][3]);
                mma_bf16(acc[mt][bt * 2 + 0], alo[mt], bhi[bt][0], bhi[bt][1]);
                mma_bf16(acc[mt][bt * 2 + 1], alo[mt], bhi[bt][2], bhi[bt][3]);
            }
        }
    }

    // ---- epilogue ----
#pragma unroll
    for (int mt = 0; mt < 2; ++mt) {
        int r0 = rowBase + warpM * 32 + mt * 16 + (lane >> 2);
#pragma unroll
        for (int j = 0; j < 8; ++j) {
            int col = colBase + warpN * 64 + j * 8 + (lane & 3) * 2;
            float bias0 = b1[col], bias1 = b1[col + 1];
            if (b2) { bias0 += b2[col]; bias1 += b2[col + 1]; }
            float v0 = acc[mt][j][0] + bias0;
            float v1 = acc[mt][j][1] + bias1;
            float v2 = acc[mt][j][2] + bias0;
            float v3 = acc[mt][j][3] + bias1;
            if (act) {
                v0 = fmaxf(v0, 0.f); v1 = fmaxf(v1, 0.f);
                v2 = fmaxf(v2, 0.f); v3 = fmaxf(v3, 0.f);
            }
            if (r0 < M)     *(float2*)(C + (size_t)r0 * ldc + col)       = make_float2(v0, v1);
            if (r0 + 8 < M) *(float2*)(C + (size_t)(r0 + 8) * ldc + col) = make_float2(v2, v3);
        }
    }
}

// ---------------- launcher ----------------------------------------------------
extern "C" void kernel_launch(void* const* d_in, const int* in_sizes, int n_in,
                              void* d_out, int out_size) {
    const float* x       = (const float*)d_in[0];
    const int*   src     = (const int*)d_in[1];
    const int*   dst     = (const int*)d_in[2];
    const int*   rel     = (const int*)d_in[3];
    const float* rel_w1  = (const float*)d_in[4];
    const float* rel_b1  = (const float*)d_in[5];
    const float* loop_w1 = (const float*)d_in[6];
    const float* loop_b1 = (const float*)d_in[7];
    const float* hp_w1   = (const float*)d_in[8];
    const float* hp_b1   = (const float*)d_in[9];
    const float* ht_w1   = (const float*)d_in[10];
    const float* ht_b1   = (const float*)d_in[11];
    const float* rel_w2  = (const float*)d_in[12];
    const float* rel_b2  = (const float*)d_in[13];
    const float* loop_w2 = (const float*)d_in[14];
    const float* loop_b2 = (const float*)d_in[15];
    const float* hp_w2   = (const float*)d_in[16];
    const float* hp_b2   = (const float*)d_in[17];
    const float* ht_w2   = (const float*)d_in[18];
    const float* ht_b2   = (const float*)d_in[19];
    float* out = (float*)d_out;

    float *agg, *cnt, *tbuf, *pg, *hbuf;
    cudaGetSymbolAddress((void**)&agg,  g_agg);
    cudaGetSymbolAddress((void**)&cnt,  g_cnt);
    cudaGetSymbolAddress((void**)&tbuf, g_t);
    cudaGetSymbolAddress((void**)&pg,   g_pg);
    cudaGetSymbolAddress((void**)&hbuf, g_h);

    const int M = NN, E = EE;
    const int TPB = 256;
    dim3 gemm_grid((M + 127) / 128, DH / 128);   // (391, 2)

    // ---- counts (identical for both layers) ----
    zero_kernel<<<(NN * RR / 4 + TPB - 1) / TPB, TPB>>>((float4*)cnt, NN * RR / 4);
    count_kernel<<<(E + TPB - 1) / TPB, TPB>>>(dst, rel, E);

    // ---- layer 1: RGC(128 -> 256) ----
    {
        int n4 = NN * RR * DIN / 4;
        zero_kernel<<<(n4 + TPB - 1) / TPB, TPB>>>((float4*)agg, n4);
    }
    scatter_kernel<DIN><<<(E * 32 + TPB - 1) / TPB, TPB>>>(x, src, dst, rel, E);
    scale_kernel<DIN><<<(NN * RR * (DIN / 4) + TPB - 1) / TPB, TPB>>>(NN * RR);
    gemm_mma<<<gemm_grid, TPB>>>(agg, RR * DIN, rel_w1, x, DIN, loop_w1,
                                 rel_b1, loop_b1, tbuf, M, DH, 1);
    gemm_mma<<<gemm_grid, TPB>>>(tbuf, DH, hp_w1, nullptr, 0, nullptr,
                                 hp_b1, nullptr, pg, M, 2 * DH, 0);
    gemm_mma<<<gemm_grid, TPB>>>(tbuf, DH, ht_w1, nullptr, 0, nullptr,
                                 ht_b1, nullptr, pg + DH, M, 2 * DH, 0);
    highway_kernel<<<(M * DH + TPB - 1) / TPB, TPB>>>(tbuf, pg, hbuf, M);

    // ---- layer 2: RGC(256 -> 256) ----
    {
        int n4 = NN * RR * DH / 4;
        zero_kernel<<<(n4 + TPB - 1) / TPB, TPB>>>((float4*)agg, n4);
    }
    scatter_kernel<DH><<<(E * 32 + TPB - 1) / TPB, TPB>>>(hbuf, src, dst, rel, E);
    scale_kernel<DH><<<(NN * RR * (DH / 4) + TPB - 1) / TPB, TPB>>>(NN * RR);
    gemm_mma<<<gemm_grid, TPB>>>(agg, RR * DH, rel_w2, hbuf, DH, loop_w2,
                                 rel_b2, loop_b2, tbuf, M, DH, 1);
    gemm_mma<<<gemm_grid, TPB>>>(tbuf, DH, hp_w2, nullptr, 0, nullptr,
                                 hp_b2, nullptr, pg, M, 2 * DH, 0);
    gemm_mma<<<gemm_grid, TPB>>>(tbuf, DH, ht_w2, nullptr, 0, nullptr,
                                 ht_b2, nullptr, pg + DH, M, 2 * DH, 0);
    highway_kernel<<<(M * DH + TPB - 1) / TPB, TPB>>>(tbuf, pg, out, M);
}

// round 4
// speedup vs baseline: 3.1041x; 1.7284x over previous
#include <cuda_runtime.h>
#include <cuda_bf16.h>
#include <cstdint>
#include <cstddef>

#define NN   50000
#define EE   800000
#define RR   4
#define NB   (NN * RR)          // 200000 buckets
#define DIN  128
#define DH   256
#define EPSF 1e-10f

// ---------------- scratch (static device globals; no cudaMalloc allowed) ----
__device__ int   g_deg[NB];
__device__ int   g_off[NB];
__device__ int   g_pos[NB];
__device__ int   g_bsum[256];
__device__ int   g_eidx[EE];
__device__ float g_agg[(size_t)NN * RR * DH];
__device__ float g_t[(size_t)NN * DH];
__device__ float g_pg[(size_t)NN * 2 * DH];
__device__ float g_h[(size_t)NN * DH];

// pre-split weights (bf16 hi/lo), concatenated
#define OW_REL1  0
#define OW_LOOP1 131072
#define OW_HP1   163840
#define OW_HT1   229376
#define OW_REL2  294912
#define OW_LOOP2 557056
#define OW_HP2   622592
#define OW_HT2   688128
#define WTOT     753664
__device__ uint16_t g_whi[WTOT];
__device__ uint16_t g_wlo[WTOT];

// ---------------- CSR build ----------------------------------------------------
__global__ void zero_i(int* __restrict__ p, int n) {
    int i = blockIdx.x * blockDim.x + threadIdx.x;
    if (i < n) p[i] = 0;
}

__global__ void count_kernel(const int* __restrict__ dst, const int* __restrict__ rel, int E) {
    int e = blockIdx.x * blockDim.x + threadIdx.x;
    if (e < E) atomicAdd(&g_deg[dst[e] * RR + rel[e]], 1);
}

// block-level exclusive scan: 1024 elems/block (256 thr x 4). bsum optional.
__global__ void scan_block(const int* __restrict__ in, int* __restrict__ out,
                           int* __restrict__ bsum, int n) {
    __shared__ int wsum[8];
    int base = blockIdx.x * 1024;
    int t = threadIdx.x;
    int lane = t & 31, w = t >> 5;
    int v[4], s = 0;
#pragma unroll
    for (int j = 0; j < 4; j++) {
        int i = base + t * 4 + j;
        v[j] = (i < n) ? in[i] : 0;
        s += v[j];
    }
    int ps = s;
#pragma unroll
    for (int d = 1; d < 32; d <<= 1) {
        int y = __shfl_up_sync(~0u, ps, d);
        if (lane >= d) ps += y;
    }
    if (lane == 31) wsum[w] = ps;
    __syncthreads();
    if (w == 0) {
        int x = (lane < 8) ? wsum[lane] : 0;
#pragma unroll
        for (int d = 1; d < 8; d <<= 1) {
            int y = __shfl_up_sync(~0u, x, d);
            if (lane >= d) x += y;
        }
        if (lane < 8) wsum[lane] = x;
    }
    __syncthreads();
    int excl = ps - s + (w > 0 ? wsum[w - 1] : 0);
#pragma unroll
    for (int j = 0; j < 4; j++) {
        int i = base + t * 4 + j;
        if (i < n) out[i] = excl;
        excl += v[j];
    }
    if (t == 255 && bsum) bsum[blockIdx.x] = (w > 0 ? wsum[w - 1] : 0) + ps;
}

__global__ void scan_add(int* __restrict__ off, const int* __restrict__ bsum, int n) {
    int i = blockIdx.x * 1024 + threadIdx.x * 4;
    int a = bsum[blockIdx.x];
#pragma unroll
    for (int j = 0; j < 4; j++)
        if (i + j < n) off[i + j] += a;
}

__global__ void place_kernel(const int* __restrict__ src, const int* __restrict__ dst,
                             const int* __restrict__ rel, int E) {
    int e = blockIdx.x * blockDim.x + threadIdx.x;
    if (e >= E) return;
    int b = dst[e] * RR + rel[e];
    int slot = g_off[b] + atomicAdd(&g_pos[b], 1);
    g_eidx[slot] = src[e];
}

// ---------------- gather aggregation (one warp per bucket, mean folded in) -----
template <int D>
__global__ void agg_gather(const float* __restrict__ x) {
    int gw = (blockIdx.x * blockDim.x + threadIdx.x) >> 5;
    int lane = threadIdx.x & 31;
    if (gw >= NB) return;
    int start = g_off[gw];
    int n = g_deg[gw];
    const float4* X = (const float4*)x;
    float4 a0 = make_float4(0.f, 0.f, 0.f, 0.f);
    float4 a1 = make_float4(0.f, 0.f, 0.f, 0.f);
    int k = 0;
    for (; k + 2 <= n; k += 2) {
        int s0 = g_eidx[start + k];
        int s1 = g_eidx[start + k + 1];
        const float4* r0 = X + (size_t)s0 * (D / 4);
        const float4* r1 = X + (size_t)s1 * (D / 4);
        float4 v0 = r0[lane], w0 = r1[lane];
        a0.x += v0.x + w0.x; a0.y += v0.y + w0.y;
        a0.z += v0.z + w0.z; a0.w += v0.w + w0.w;
        if (D == 256) {
            float4 v1 = r0[lane + 32], w1 = r1[lane + 32];
            a1.x += v1.x + w1.x; a1.y += v1.y + w1.y;
            a1.z += v1.z + w1.z; a1.w += v1.w + w1.w;
        }
    }
    if (k < n) {
        int s0 = g_eidx[start + k];
        const float4* r0 = X + (size_t)s0 * (D / 4);
        float4 v0 = r0[lane];
        a0.x += v0.x; a0.y += v0.y; a0.z += v0.z; a0.w += v0.w;
        if (D == 256) {
            float4 v1 = r0[lane + 32];
            a1.x += v1.x; a1.y += v1.y; a1.z += v1.z; a1.w += v1.w;
        }
    }
    float inv = 1.0f / ((float)n + EPSF);
    a0.x *= inv; a0.y *= inv; a0.z *= inv; a0.w *= inv;
    float4* out = (float4*)(g_agg + (size_t)gw * D);
    out[lane] = a0;
    if (D == 256) {
        a1.x *= inv; a1.y *= inv; a1.z *= inv; a1.w *= inv;
        out[lane + 32] = a1;
    }
}

// ---------------- weight pre-split ---------------------------------------------
__global__ void split_w(const float* __restrict__ w, uint16_t* __restrict__ hi,
                        uint16_t* __restrict__ lo, int n) {
    int i = blockIdx.x * blockDim.x + threadIdx.x;
    if (i >= n) return;
    float v = w[i];
    __nv_bfloat16 h = __float2bfloat16_rn(v);
    hi[i] = __bfloat16_as_ushort(h);
    lo[i] = __bfloat16_as_ushort(__float2bfloat16_rn(v - __bfloat162float(h)));
}

// ---------------- highway elementwise ------------------------------------------
__global__ void highway_kernel(const float* __restrict__ t, const float* __restrict__ pg,
                               float* __restrict__ h, int M) {
    int i = blockIdx.x * blockDim.x + threadIdx.x;
    if (i >= M * DH) return;
    int n = i >> 8;
    int c = i & 255;
    float p = pg[(size_t)n * (2 * DH) + c];
    float g = pg[(size_t)n * (2 * DH) + DH + c];
    p = fmaxf(p, 0.0f);
    g = 1.0f / (1.0f + expf(-g));
    h[i] = g * p + (1.0f - g) * t[i];
}

// ---------------- mma.sync bf16 helpers ------------------------------------------
__device__ __forceinline__ uint32_t smem_u32(const void* p) {
    uint32_t a;
    asm("{ .reg .u64 t; cvta.to.shared.u64 t, %1; cvt.u32.u64 %0, t; }" : "=r"(a) : "l"(p));
    return a;
}
__device__ __forceinline__ void ldsm_x4(uint32_t* r, uint32_t addr) {
    asm volatile("ldmatrix.sync.aligned.m8n8.x4.shared.b16 {%0,%1,%2,%3}, [%4];"
                 : "=r"(r[0]), "=r"(r[1]), "=r"(r[2]), "=r"(r[3]) : "r"(addr));
}
__device__ __forceinline__ void ldsm_x4_t(uint32_t* r, uint32_t addr) {
    asm volatile("ldmatrix.sync.aligned.m8n8.x4.trans.shared.b16 {%0,%1,%2,%3}, [%4];"
                 : "=r"(r[0]), "=r"(r[1]), "=r"(r[2]), "=r"(r[3]) : "r"(addr));
}
__device__ __forceinline__ void mma_bf16(float* d, const uint32_t* a, uint32_t b0, uint32_t b1) {
    asm volatile(
        "mma.sync.aligned.m16n8k16.row.col.f32.bf16.bf16.f32 "
        "{%0,%1,%2,%3}, {%4,%5,%6,%7}, {%8,%9}, {%0,%1,%2,%3};"
        : "+f"(d[0]), "+f"(d[1]), "+f"(d[2]), "+f"(d[3])
        : "r"(a[0]), "r"(a[1]), "r"(a[2]), "r"(a[3]), "r"(b0), "r"(b1));
}
__device__ __forceinline__ void split_bf(float v, uint16_t& h, uint16_t& l) {
    __nv_bfloat16 hb = __float2bfloat16_rn(v);
    float res = v - __bfloat162float(hb);
    h = __bfloat16_as_ushort(hb);
    l = __bfloat16_as_ushort(__float2bfloat16_rn(res));
}
__device__ __forceinline__ void split4(float4 v, uint2& hi, uint2& lo) {
    uint16_t h0, h1, h2, h3, l0, l1, l2, l3;
    split_bf(v.x, h0, l0); split_bf(v.y, h1, l1);
    split_bf(v.z, h2, l2); split_bf(v.w, h3, l3);
    hi.x = (uint32_t)h0 | ((uint32_t)h1 << 16);
    hi.y = (uint32_t)h2 | ((uint32_t)h3 << 16);
    lo.x = (uint32_t)l0 | ((uint32_t)l1 << 16);
    lo.y = (uint32_t)l2 | ((uint32_t)l3 << 16);
}

// ---------------- bf16-split dual-A GEMM -----------------------------------------
// C = act( A1[M,K1] @ W1 + A2[M,K2] @ W2 + b1 (+b2) ), W pre-split bf16 hi/lo
#define A_STRIDE 80
#define A_BYTES  (128 * A_STRIDE)
#define B_BYTES  (32 * 256)
#define STAGE_BYTES (A_BYTES + B_BYTES)

__global__ void __launch_bounds__(256)
gemm_mma(const float* __restrict__ A1, int K1,
         const uint16_t* __restrict__ W1h, const uint16_t* __restrict__ W1l,
         const float* __restrict__ A2, int K2,
         const uint16_t* __restrict__ W2h, const uint16_t* __restrict__ W2l,
         const float* __restrict__ b1, const float* __restrict__ b2,
         float* __restrict__ C, int M, int ldc, int act) {
    __shared__ char sm[2 * STAGE_BYTES];

    int tid  = threadIdx.x;
    int warp = tid >> 5;
    int lane = tid & 31;
    int warpM = warp >> 1;
    int warpN = warp & 1;
    int rowBase = blockIdx.x * 128;
    int colBase = blockIdx.y * 128;

    float acc[2][8][4];
#pragma unroll
    for (int i = 0; i < 2; i++)
#pragma unroll
        for (int j = 0; j < 8; j++)
#pragma unroll
            for (int q = 0; q < 4; q++) acc[i][j][q] = 0.f;

    int nt1 = K1 >> 4, nt2 = K2 >> 4;
    int nt = nt1 + nt2;

    float4 av[2];
    uint2 bhv[2], blv[2];

    // prefetch t = 0
    {
        const float* A = A1; const uint16_t* Wh = W1h; const uint16_t* Wl = W1l;
        int K = K1, k0 = 0;
        if (nt1 == 0) { A = A2; Wh = W2h; Wl = W2l; K = K2; }
#pragma unroll
        for (int i = 0; i < 2; ++i) {
            int li = tid + i * 256;
            int r = li >> 2, c4 = li & 3;
            int gr = rowBase + r;
            av[i] = (gr < M) ? *(const float4*)(A + (size_t)gr * K + k0 + c4 * 4)
                             : make_float4(0.f, 0.f, 0.f, 0.f);
        }
#pragma unroll
        for (int i = 0; i < 2; ++i) {
            int li = tid + i * 256;
            int r = li >> 5, c4 = li & 31;
            size_t wi = (size_t)(k0 + r) * DH + colBase + c4 * 4;
            bhv[i] = *(const uint2*)(Wh + wi);
            blv[i] = *(const uint2*)(Wl + wi);
        }
    }

    for (int t = 0; t < nt; ++t) {
        char* As = sm + (t & 1) * STAGE_BYTES;
        char* Bs = As + A_BYTES;

        // ---- STS ----
#pragma unroll
        for (int i = 0; i < 2; ++i) {
            int li = tid + i * 256;
            int r = li >> 2, c4 = li & 3;
            uint2 hi, lo;
            split4(av[i], hi, lo);
            *(uint2*)(As + r * A_STRIDE + c4 * 8)      = hi;
            *(uint2*)(As + r * A_STRIDE + 32 + c4 * 8) = lo;
        }
#pragma unroll
        for (int i = 0; i < 2; ++i) {
            int li = tid + i * 256;
            int r = li >> 5, c4 = li & 31;
            uint32_t sw = (uint32_t)(c4 * 8) ^ ((r & 7) << 4);
            *(uint2*)(Bs + r * 256 + sw)        = bhv[i];
            *(uint2*)(Bs + (16 + r) * 256 + sw) = blv[i];
        }
        __syncthreads();

        // ---- prefetch t+1 ----
        if (t + 1 < nt) {
            int tn = t + 1;
            const float* A; const uint16_t* Wh; const uint16_t* Wl; int K, k0;
            if (tn < nt1) { A = A1; Wh = W1h; Wl = W1l; K = K1; k0 = tn * 16; }
            else          { A = A2; Wh = W2h; Wl = W2l; K = K2; k0 = (tn - nt1) * 16; }
#pragma unroll
            for (int i = 0; i < 2; ++i) {
                int li = tid + i * 256;
                int r = li >> 2, c4 = li & 3;
                int gr = rowBase + r;
                av[i] = (gr < M) ? *(const float4*)(A + (size_t)gr * K + k0 + c4 * 4)
                                 : make_float4(0.f, 0.f, 0.f, 0.f);
            }
#pragma unroll
            for (int i = 0; i < 2; ++i) {
                int li = tid + i * 256;
                int r = li >> 5, c4 = li & 31;
                size_t wi = (size_t)(k0 + r) * DH + colBase + c4 * 4;
                bhv[i] = *(const uint2*)(Wh + wi);
                blv[i] = *(const uint2*)(Wl + wi);
            }
        }

        // ---- fragments ----
        uint32_t aBase = smem_u32(As);
        uint32_t bBase = smem_u32(Bs);
        uint32_t ahi[2][4], alo[2][4], bhi[4][4], blo[4][4];
#pragma unroll
        for (int mt = 0; mt < 2; ++mt) {
            int row = warpM * 32 + mt * 16 + (lane & 15);
            uint32_t ad = aBase + row * A_STRIDE + ((lane >> 4) * 8) * 2;
            ldsm_x4(ahi[mt], ad);
            ldsm_x4(alo[mt], ad + 32);
        }
#pragma unroll
        for (int bt = 0; bt < 4; ++bt) {
            int k = lane & 15;
            uint32_t cb = (uint32_t)(warpN * 128 + bt * 32 + (lane >> 4) * 16);
            uint32_t bd = bBase + k * 256 + (cb ^ ((k & 7) << 4));
            ldsm_x4_t(bhi[bt], bd);
            ldsm_x4_t(blo[bt], bd + 16 * 256);
        }

        // ---- 3-term split mma ----
#pragma unroll
        for (int mt = 0; mt < 2; ++mt) {
#pragma unroll
            for (int bt = 0; bt < 4; ++bt) {
                mma_bf16(acc[mt][bt * 2 + 0], ahi[mt], bhi[bt][0], bhi[bt][1]);
                mma_bf16(acc[mt][bt * 2 + 1], ahi[mt], bhi[bt][2], bhi[bt][3]);
                mma_bf16(acc[mt][bt * 2 + 0], ahi[mt], blo[bt][0], blo[bt][1]);
                mma_bf16(acc[mt][bt * 2 + 1], ahi[mt], blo[bt][2], blo[bt][3]);
                mma_bf16(acc[mt][bt * 2 + 0], alo[mt], bhi[bt][0], bhi[bt][1]);
                mma_bf16(acc[mt][bt * 2 + 1], alo[mt], bhi[bt][2], bhi[bt][3]);
            }
        }
    }

    // ---- epilogue ----
#pragma unroll
    for (int mt = 0; mt < 2; ++mt) {
        int r0 = rowBase + warpM * 32 + mt * 16 + (lane >> 2);
#pragma unroll
        for (int j = 0; j < 8; ++j) {
            int col = colBase + warpN * 64 + j * 8 + (lane & 3) * 2;
            float bias0 = b1[col], bias1 = b1[col + 1];
            if (b2) { bias0 += b2[col]; bias1 += b2[col + 1]; }
            float v0 = acc[mt][j][0] + bias0;
            float v1 = acc[mt][j][1] + bias1;
            float v2 = acc[mt][j][2] + bias0;
            float v3 = acc[mt][j][3] + bias1;
            if (act) {
                v0 = fmaxf(v0, 0.f); v1 = fmaxf(v1, 0.f);
                v2 = fmaxf(v2, 0.f); v3 = fmaxf(v3, 0.f);
            }
            if (r0 < M)     *(float2*)(C + (size_t)r0 * ldc + col)       = make_float2(v0, v1);
            if (r0 + 8 < M) *(float2*)(C + (size_t)(r0 + 8) * ldc + col) = make_float2(v2, v3);
        }
    }
}

// ---------------- launcher ----------------------------------------------------
extern "C" void kernel_launch(void* const* d_in, const int* in_sizes, int n_in,
                              void* d_out, int out_size) {
    const float* x       = (const float*)d_in[0];
    const int*   src     = (const int*)d_in[1];
    const int*   dst     = (const int*)d_in[2];
    const int*   rel     = (const int*)d_in[3];
    const float* rel_w1  = (const float*)d_in[4];
    const float* rel_b1  = (const float*)d_in[5];
    const float* loop_w1 = (const float*)d_in[6];
    const float* loop_b1 = (const float*)d_in[7];
    const float* hp_w1   = (const float*)d_in[8];
    const float* hp_b1   = (const float*)d_in[9];
    const float* ht_w1   = (const float*)d_in[10];
    const float* ht_b1   = (const float*)d_in[11];
    const float* rel_w2  = (const float*)d_in[12];
    const float* rel_b2  = (const float*)d_in[13];
    const float* loop_w2 = (const float*)d_in[14];
    const float* loop_b2 = (const float*)d_in[15];
    const float* hp_w2   = (const float*)d_in[16];
    const float* hp_b2   = (const float*)d_in[17];
    const float* ht_w2   = (const float*)d_in[18];
    const float* ht_b2   = (const float*)d_in[19];
    float* out = (float*)d_out;

    float *agg, *tbuf, *pg, *hbuf;
    int *deg, *off, *pos, *bsum;
    uint16_t *whi, *wlo;
    cudaGetSymbolAddress((void**)&agg,  g_agg);
    cudaGetSymbolAddress((void**)&tbuf, g_t);
    cudaGetSymbolAddress((void**)&pg,   g_pg);
    cudaGetSymbolAddress((void**)&hbuf, g_h);
    cudaGetSymbolAddress((void**)&deg,  g_deg);
    cudaGetSymbolAddress((void**)&off,  g_off);
    cudaGetSymbolAddress((void**)&pos,  g_pos);
    cudaGetSymbolAddress((void**)&bsum, g_bsum);
    cudaGetSymbolAddress((void**)&whi,  g_whi);
    cudaGetSymbolAddress((void**)&wlo,  g_wlo);

    const int M = NN, E = EE;
    const int TPB = 256;
    const int NBLK = (NB + 1023) / 1024;            // 196
    dim3 gemm_grid((M + 127) / 128, DH / 128);      // (391, 2)
    int agg_grid = (NB * 32 + TPB - 1) / TPB;       // 25000

    // ---- CSR build (graph static across both layers) ----
    zero_i<<<(NB + TPB - 1) / TPB, TPB>>>(deg, NB);
    zero_i<<<(NB + TPB - 1) / TPB, TPB>>>(pos, NB);
    count_kernel<<<(E + TPB - 1) / TPB, TPB>>>(dst, rel, E);
    scan_block<<<NBLK, 256>>>(deg, off, bsum, NB);
    scan_block<<<1, 256>>>(bsum, bsum, nullptr, NBLK);
    scan_add<<<NBLK, 256>>>(off, bsum, NB);
    place_kernel<<<(E + TPB - 1) / TPB, TPB>>>(src, dst, rel, E);

    // ---- pre-split all weights to bf16 hi/lo ----
    split_w<<<(131072 + 255) / 256, 256>>>(rel_w1,  whi + OW_REL1,  wlo + OW_REL1,  131072);
    split_w<<<(32768  + 255) / 256, 256>>>(loop_w1, whi + OW_LOOP1, wlo + OW_LOOP1, 32768);
    split_w<<<(65536  + 255) / 256, 256>>>(hp_w1,   whi + OW_HP1,   wlo + OW_HP1,   65536);
    split_w<<<(65536  + 255) / 256, 256>>>(ht_w1,   whi + OW_HT1,   wlo + OW_HT1,   65536);
    split_w<<<(262144 + 255) / 256, 256>>>(rel_w2,  whi + OW_REL2,  wlo + OW_REL2,  262144);
    split_w<<<(65536  + 255) / 256, 256>>>(loop_w2, whi + OW_LOOP2, wlo + OW_LOOP2, 65536);
    split_w<<<(65536  + 255) / 256, 256>>>(hp_w2,   whi + OW_HP2,   wlo + OW_HP2,   65536);
    split_w<<<(65536  + 255) / 256, 256>>>(ht_w2,   whi + OW_HT2,   wlo + OW_HT2,   65536);

    // ---- layer 1: RGC(128 -> 256) ----
    agg_gather<DIN><<<agg_grid, TPB>>>(x);
    gemm_mma<<<gemm_grid, TPB>>>(agg, RR * DIN, whi + OW_REL1, wlo + OW_REL1,
                                 x, DIN, whi + OW_LOOP1, wlo + OW_LOOP1,
                                 rel_b1, loop_b1, tbuf, M, DH, 1);
    gemm_mma<<<gemm_grid, TPB>>>(tbuf, DH, whi + OW_HP1, wlo + OW_HP1,
                                 nullptr, 0, nullptr, nullptr,
                                 hp_b1, nullptr, pg, M, 2 * DH, 0);
    gemm_mma<<<gemm_grid, TPB>>>(tbuf, DH, whi + OW_HT1, wlo + OW_HT1,
                                 nullptr, 0, nullptr, nullptr,
                                 ht_b1, nullptr, pg + DH, M, 2 * DH, 0);
    highway_kernel<<<(M * DH + TPB - 1) / TPB, TPB>>>(tbuf, pg, hbuf, M);

    // ---- layer 2: RGC(256 -> 256) ----
    agg_gather<DH><<<agg_grid, TPB>>>(hbuf);
    gemm_mma<<<gemm_grid, TPB>>>(agg, RR * DH, whi + OW_REL2, wlo + OW_REL2,
                                 hbuf, DH, whi + OW_LOOP2, wlo + OW_LOOP2,
                                 rel_b2, loop_b2, tbuf, M, DH, 1);
    gemm_mma<<<gemm_grid, TPB>>>(tbuf, DH, whi + OW_HP2, wlo + OW_HP2,
                                 nullptr, 0, nullptr, nullptr,
                                 hp_b2, nullptr, pg, M, 2 * DH, 0);
    gemm_mma<<<gemm_grid, TPB>>>(tbuf, DH, whi + OW_HT2, wlo + OW_HT2,
                                 nullptr, 0, nullptr, nullptr,
                                 ht_b2, nullptr, pg + DH, M, 2 * DH, 0);
    highway_kernel<<<(M * DH + TPB - 1) / TPB, TPB>>>(tbuf, pg, out, M);
}